// round 7
// baseline (speedup 1.0000x reference)
#include <cuda_runtime.h>
#include <cstdint>

typedef unsigned long long u64;
typedef unsigned int u32;

#define NIMG   8
#define NANCH  25200
#define NCH    85
#define NC     80
#define CONF   0.96f
#define IOUT   0.45f
#define CLSCAP 64
#define KEPTCAP 4096
#define DETS   300
#define NBIN   4096
#define CONTCAP 1024
#define SB0    0x3F75C290u   // smallest float bits with s > 0.96f
#define FULL   0xFFFFFFFFu
#define APT    4             // anchors per thread in filter
#define NBLK_Y 10            // nms blocks per image (8 classes each)

// Device scratch (zero-initialized; kernels reset counters after last use so
// every graph replay starts clean).
__device__ int g_ccount[NIMG * NC];
__device__ u64 g_clist[NIMG * NC * CLSCAP];
__device__ int g_kcount[NIMG];
__device__ u64 g_kept[NIMG * KEPTCAP];
__device__ int g_ticket[NIMG];

// ---------------------------------------------------------------------------
// K1: filter. Each thread front-loads APT independent obj values (MLP=4),
// block compacts hits into smem, then 8 warps expand hits in parallel
// (classes across lanes), scattering candidate keys into per-(image,class)
// lists. Key = (score_bits << 32) | ~flat_idx -> desc order == jax top_k.
// ---------------------------------------------------------------------------
__global__ __launch_bounds__(256) void k_filter(const float* __restrict__ pred) {
    __shared__ int   s_anch[1024];
    __shared__ float s_obj[1024];
    __shared__ int   s_n;

    int img  = blockIdx.y;
    int base = blockIdx.x * (256 * APT) + threadIdx.x * APT;
    int warp = threadIdx.x >> 5;
    int lane = threadIdx.x & 31;

    if (threadIdx.x == 0) s_n = 0;

    float obj[APT];
    #pragma unroll
    for (int r = 0; r < APT; r++) {
        int a = base + r;
        obj[r] = (a < NANCH)
               ? __ldg(pred + ((size_t)img * NANCH + a) * NCH + 4) : 0.f;
    }
    __syncthreads();

    #pragma unroll
    for (int r = 0; r < APT; r++) {
        if (obj[r] > CONF) {
            int p = atomicAdd(&s_n, 1);
            s_anch[p] = base + r;
            s_obj[p]  = obj[r];
        }
    }
    __syncthreads();

    int n = s_n;
    for (int j = warp; j < n; j += 8) {
        int   a = s_anch[j];
        float o = s_obj[j];
        const float* row = pred + ((size_t)img * NANCH + a) * NCH + 5;
        #pragma unroll
        for (int r = 0; r < 3; r++) {
            int c = lane + r * 32;
            float s = (c < NC) ? __ldg(row + c) * o : 0.f;
            if (s > CONF) {
                int pos = atomicAdd(&g_ccount[img * NC + c], 1);
                if (pos < CLSCAP) {
                    u32 idx = (u32)(a * NC + c);
                    g_clist[(img * NC + c) * CLSCAP + pos] =
                        ((u64)__float_as_uint(s) << 32) | (u32)(~idx);
                }
            }
        }
    }
}

// Warp-register bitonic compare-exchange step.
__device__ __forceinline__ u64 ce(u64 v, int j, bool desc, int lane) {
    u64 q = __shfl_xor_sync(FULL, v, j);
    bool keepmax = (((lane & j) == 0) == desc);
    bool vbig = v > q;
    return (keepmax == vbig) ? v : q;
}

__device__ __forceinline__ void decode_box(const float* __restrict__ pred,
                                           int img, u64 key, bool valid,
                                           float& x1, float& y1,
                                           float& x2, float& y2) {
    if (valid) {
        u32 idx = ~(u32)key;
        int a = idx / NC;
        const float* p = pred + ((size_t)img * NANCH + a) * NCH;
        float cx = __ldg(p), cy = __ldg(p + 1);
        float w  = __ldg(p + 2), h = __ldg(p + 3);
        x1 = cx - 0.5f * w; y1 = cy - 0.5f * h;
        x2 = cx + 0.5f * w; y2 = cy + 0.5f * h;
    } else { x1 = y1 = x2 = y2 = 0.f; }
}

// ---------------------------------------------------------------------------
// K2 (fused NMS + output): grid (NIMG, 10), 256 threads. Each warp handles
// one (image, class): register sort + greedy NMS (cross-class IoU == 0
// exactly due to the label*4 offset), appending kept keys to the per-image
// global list. The LAST block per image (global ticket) then runs the output
// phase: histogram + suffix scan -> contenders -> exact brute-force rank ->
// emit + zero-fill, and resets counters for the next graph replay.
// ---------------------------------------------------------------------------
__global__ __launch_bounds__(256) void k_nms_out(const float* __restrict__ pred,
                                                 float* __restrict__ out) {
    __shared__ u32 hist[NBIN];
    __shared__ u64 s_cont[CONTCAP];
    __shared__ u32 wsums[8];
    __shared__ int s_ccnt;
    __shared__ int s_last;

    int img  = blockIdx.x;
    int tid  = threadIdx.x;
    int warp = tid >> 5;
    int lane = tid & 31;
    int c    = blockIdx.y * 8 + warp;

    // ---------------- NMS for this warp's class ----------------
    int cnt = g_ccount[img * NC + c];
    if (cnt > CLSCAP) cnt = CLSCAP;
    if (lane == 0) g_ccount[img * NC + c] = 0;  // clean for next replay

    if (cnt > 0) {
        const u64* lst = &g_clist[(img * NC + c) * CLSCAP];
        if (cnt <= 32) {
            // fast path: 32-element register sort + NMS
            u64 k0 = (lane < cnt) ? lst[lane] : 0ull;
            #pragma unroll
            for (int k = 2; k <= 16; k <<= 1) {
                #pragma unroll
                for (int j = k >> 1; j > 0; j >>= 1)
                    k0 = ce(k0, j, ((lane & k) == 0), lane);
            }
            #pragma unroll
            for (int j = 16; j > 0; j >>= 1)
                k0 = ce(k0, j, true, lane);

            float x1, y1, x2, y2;
            decode_box(pred, img, k0, lane < cnt, x1, y1, x2, y2);

            u32 alive = (cnt >= 32) ? FULL : ((1u << cnt) - 1u);
            for (int i = 0; i < cnt; i++) {
                if (!((alive >> i) & 1u)) continue;
                float ax1 = __shfl_sync(FULL, x1, i);
                float ay1 = __shfl_sync(FULL, y1, i);
                float ax2 = __shfl_sync(FULL, x2, i);
                float ay2 = __shfl_sync(FULL, y2, i);
                float areaA = (ax2 - ax1) * (ay2 - ay1);
                float iw = fminf(ax2, x2) - fmaxf(ax1, x1);
                float ih = fminf(ay2, y2) - fmaxf(ay1, y1);
                float in0 = fmaxf(iw, 0.f) * fmaxf(ih, 0.f);
                float ar = (x2 - x1) * (y2 - y1);
                float iou = in0 / (areaA + ar - in0 + 1e-9f);
                u32 m = __ballot_sync(FULL, (lane > i) && (iou > IOUT));
                alive &= ~m;
            }

            int tot = __popc(alive);
            int bs = 0;
            if (lane == 0) bs = atomicAdd(&g_kcount[img], tot);
            bs = __shfl_sync(FULL, bs, 0);
            if ((alive >> lane) & 1u) {
                int p = bs + __popc(alive & ((1u << lane) - 1u));
                if (p < KEPTCAP) g_kept[img * KEPTCAP + p] = k0;
            }
        } else {
            // slow path: 64-element sort + NMS
            u64 k0 = lst[lane];
            u64 k1 = (lane + 32 < cnt) ? lst[lane + 32] : 0ull;

            #pragma unroll
            for (int k = 2; k <= 16; k <<= 1) {
                #pragma unroll
                for (int j = k >> 1; j > 0; j >>= 1) {
                    bool d = ((lane & k) == 0);
                    k0 = ce(k0, j, d, lane);
                    k1 = ce(k1, j, d, lane);
                }
            }
            #pragma unroll
            for (int j = 16; j > 0; j >>= 1) {
                k0 = ce(k0, j, true, lane);
                k1 = ce(k1, j, false, lane);
            }
            {
                u64 lo = (k0 < k1) ? k0 : k1;
                u64 hi = (k0 < k1) ? k1 : k0;
                k0 = hi; k1 = lo;
            }
            #pragma unroll
            for (int j = 16; j > 0; j >>= 1) {
                k0 = ce(k0, j, true, lane);
                k1 = ce(k1, j, true, lane);
            }

            float x10, y10, x20, y20, x11, y11, x21, y21;
            decode_box(pred, img, k0, true,            x10, y10, x20, y20);
            decode_box(pred, img, k1, lane + 32 < cnt, x11, y11, x21, y21);

            u64 alive = (cnt >= 64) ? ~0ull : ((1ull << cnt) - 1ull);
            for (int i = 0; i < cnt; i++) {
                if (!((alive >> i) & 1ull)) continue;
                bool hi = (i >= 32);
                int  sl = i & 31;
                float sx1 = hi ? x11 : x10, sy1 = hi ? y11 : y10;
                float sx2 = hi ? x21 : x20, sy2 = hi ? y21 : y20;
                float ax1 = __shfl_sync(FULL, sx1, sl);
                float ay1 = __shfl_sync(FULL, sy1, sl);
                float ax2 = __shfl_sync(FULL, sx2, sl);
                float ay2 = __shfl_sync(FULL, sy2, sl);
                float areaA = (ax2 - ax1) * (ay2 - ay1);

                float iw0 = fminf(ax2, x20) - fmaxf(ax1, x10);
                float ih0 = fminf(ay2, y20) - fmaxf(ay1, y10);
                float in0 = fmaxf(iw0, 0.f) * fmaxf(ih0, 0.f);
                float ar0 = (x20 - x10) * (y20 - y10);
                float iou0 = in0 / (areaA + ar0 - in0 + 1e-9f);

                float iw1 = fminf(ax2, x21) - fmaxf(ax1, x11);
                float ih1 = fminf(ay2, y21) - fmaxf(ay1, y11);
                float in1 = fmaxf(iw1, 0.f) * fmaxf(ih1, 0.f);
                float ar1 = (x21 - x11) * (y21 - y11);
                float iou1 = in1 / (areaA + ar1 - in1 + 1e-9f);

                u32 m0 = __ballot_sync(FULL, (lane > i) && (iou0 > IOUT));
                u32 m1 = __ballot_sync(FULL, ((lane + 32) > i) && (iou1 > IOUT));
                alive &= ~(((u64)m1 << 32) | (u64)m0);
            }

            u32 klo = (u32)alive, khi = (u32)(alive >> 32);
            int tot = __popc(klo) + __popc(khi);
            int bs = 0;
            if (lane == 0) bs = atomicAdd(&g_kcount[img], tot);
            bs = __shfl_sync(FULL, bs, 0);
            if ((klo >> lane) & 1u) {
                int p = bs + __popc(klo & ((1u << lane) - 1u));
                if (p < KEPTCAP) g_kept[img * KEPTCAP + p] = k0;
            }
            if ((khi >> lane) & 1u) {
                int p = bs + __popc(klo) + __popc(khi & ((1u << lane) - 1u));
                if (p < KEPTCAP) g_kept[img * KEPTCAP + p] = k1;
            }
        }
    }

    // ---------------- last-block ticket ----------------
    __syncthreads();
    __threadfence();
    if (tid == 0) {
        int t = atomicAdd(&g_ticket[img], 1);
        s_last = (t == NBLK_Y - 1);
        s_ccnt = 0;
    }
    __syncthreads();
    if (!s_last) return;
    __threadfence();  // acquire side: all producers fenced before ticket

    // ---------------- output phase (256 threads) ----------------
    int M = g_kcount[img];
    if (M > KEPTCAP) M = KEPTCAP;
    const u64* kp = &g_kept[img * KEPTCAP];

    for (int i = tid; i < NBIN; i += 256) hist[i] = 0;
    __syncthreads();
    for (int i = tid; i < M; i += 256) {
        u32 h = ((u32)(kp[i] >> 32) - SB0) >> 8;
        atomicAdd(&hist[h], 1u);
    }
    __syncthreads();

    // Suffix-exclusive scan over 4096 bins, 16 contiguous bins per thread.
    int b0 = tid * 16;
    u32 cb[16];
    u32 T = 0;
    #pragma unroll
    for (int i = 0; i < 16; i++) { cb[i] = hist[b0 + i]; T += cb[i]; }
    u32 v = T;
    #pragma unroll
    for (int o = 1; o < 32; o <<= 1) {
        u32 u = __shfl_down_sync(FULL, v, o);
        if (lane + o < 32) v += u;
    }
    u32 exw = v - T;                 // sum over strictly-higher lanes
    if (lane == 0) wsums[warp] = v;
    __syncthreads();
    if (tid < 8) {
        u32 wv = wsums[tid];
        u32 s = wv;
        #pragma unroll
        for (int o = 1; o < 8; o <<= 1) {
            u32 u = __shfl_down_sync(0xFFu, s, o);
            if (tid + o < 8) s += u;
        }
        wsums[tid] = s - wv;         // sum over strictly-higher warps
    }
    __syncthreads();
    u32 run = wsums[warp] + exw;     // strictly above this thread's bin range
    #pragma unroll
    for (int i = 15; i >= 0; i--) { hist[b0 + i] = run; run += cb[i]; }
    __syncthreads();

    // Contenders: rank < 300 requires strictly-above-bin count < 300.
    bool selAll = (M <= DETS);
    for (int i = tid; i < M; i += 256) {
        u64 k = kp[i];
        u32 h = ((u32)(k >> 32) - SB0) >> 8;
        if (selAll || hist[h] < DETS) {
            int p = atomicAdd(&s_ccnt, 1);
            if (p < CONTCAP) s_cont[p] = k;
        }
    }
    __syncthreads();
    int S = s_ccnt; if (S > CONTCAP) S = CONTCAP;

    // Exact rank among contenders (keys unique), emit row at rank.
    for (int i = tid; i < S; i += 256) {
        u64 key = s_cont[i];
        int rank = 0;
        for (int j = 0; j < S; j++) rank += (s_cont[j] > key) ? 1 : 0;
        if (rank < DETS) {
            u32 idx = ~(u32)key;
            int a   = idx / NC;
            int cls = idx - a * NC;
            const float* p = pred + ((size_t)img * NANCH + a) * NCH;
            float cx = __ldg(p), cy = __ldg(p + 1);
            float w  = __ldg(p + 2), h = __ldg(p + 3);
            float* o = out + ((size_t)img * DETS + rank) * 6;
            o[0] = cx - 0.5f * w; o[1] = cy - 0.5f * h;
            o[2] = cx + 0.5f * w; o[3] = cy + 0.5f * h;
            o[4] = __uint_as_float((u32)(key >> 32));
            o[5] = (float)cls;
        }
    }

    // Zero-fill rows [min(M,300), 300).
    int K = (M < DETS) ? M : DETS;
    for (int r = K + tid; r < DETS; r += 256) {
        float* o = out + ((size_t)img * DETS + r) * 6;
        o[0] = 0.f; o[1] = 0.f; o[2] = 0.f; o[3] = 0.f; o[4] = 0.f; o[5] = 0.f;
    }

    __syncthreads();
    if (tid == 0) {
        g_kcount[img] = 0;   // clean for next replay
        g_ticket[img] = 0;
    }
}

extern "C" void kernel_launch(void* const* d_in, const int* in_sizes, int n_in,
                              void* d_out, int out_size) {
    const float* pred = (const float*)d_in[0];
    float* out = (float*)d_out;

    dim3 g1((NANCH + 256 * APT - 1) / (256 * APT), NIMG);
    k_filter<<<g1, 256>>>(pred);
    k_nms_out<<<dim3(NIMG, NBLK_Y), 256>>>(pred, out);
}